// round 14
// baseline (speedup 1.0000x reference)
#include <cuda_runtime.h>
#include <cstdint>

#define F_ 256
#define T_ 128
#define D_ 6
#define U_ 16
#define NB_ 64
#define N_ 768
#define BROWS 16        // batch rows per CTA (2 CTAs/SM)
#define CCOLS 192       // 32 trees * 6 cols per chunk
#define NPAIR 96        // col-pairs per chunk
#define NCHUNK 4
#define THREADS 256
#define SELK 32         // k-steps per sel tile
#define NKB 8           // sel tiles per chunk
#define SEL_LD 68       // sel tile row stride: 64 data + 4 pad (colg 12 banks apart)
#define P_LD 197        // p tile row stride (odd -> conflict-free)
#define XT_LD 20        // transposed-x row stride (16 rows + 4 pad)

// Selector after sparsemax, PAIR-PACKED: g_sel_p[(jp*F_ + f)*2 + (d&1)],
// jp = t*3 + d/2. One jp row = 512 contiguous floats.
__device__ float g_sel_p[(N_ / 2) * F_ * 2];

typedef unsigned long long u64;

__device__ __forceinline__ float f4get(const float4& v, int i) {
    return i == 0 ? v.x : (i == 1 ? v.y : (i == 2 ? v.z : v.w));
}
__device__ __forceinline__ u64 pk(float lo, float hi) {
    u64 r; asm("mov.b64 %0, {%1, %2};" : "=l"(r) : "f"(lo), "f"(hi)); return r;
}
__device__ __forceinline__ u64 pkdup(float v) { return pk(v, v); }
__device__ __forceinline__ u64 mul2(u64 a, u64 b) {
    u64 d; asm("mul.rn.f32x2 %0, %1, %2;" : "=l"(d) : "l"(a), "l"(b)); return d;
}
__device__ __forceinline__ u64 fma2(u64 a, u64 b, u64 c) {
    u64 d; asm("fma.rn.f32x2 %0, %1, %2, %3;" : "=l"(d) : "l"(a), "l"(b), "l"(c)); return d;
}
__device__ __forceinline__ float lo32(u64 v) { return __uint_as_float((unsigned)(v & 0xffffffffull)); }
__device__ __forceinline__ float hi32(u64 v) { return __uint_as_float((unsigned)(v >> 32)); }

__device__ __forceinline__ uint32_t smem_u32(const void* p) {
    uint32_t a;
    asm("{ .reg .u64 t; cvta.to.shared.u64 t, %1; cvt.u32.u64 %0, t; }"
        : "=r"(a) : "l"(p));
    return a;
}
__device__ __forceinline__ void cpa16(uint32_t dst, const float* src) {
    asm volatile("cp.async.cg.shared.global [%0], [%1], 16;" :: "r"(dst), "l"(src));
}
#define CP_COMMIT() asm volatile("cp.async.commit_group;" ::: "memory")
#define CP_WAIT0()  asm volatile("cp.async.wait_group 0;" ::: "memory")

// ---------------------------------------------------------------------------
// Kernel 1: sparsemax over last axis (D=6); writes pair-packed selector.
// ---------------------------------------------------------------------------
__global__ __launch_bounds__(256) void sparsemax_kernel(const float* __restrict__ fsl) {
    int idx = blockIdx.x * blockDim.x + threadIdx.x;
    if (idx >= F_ * T_) return;
    const int f = idx >> 7;
    const int t = idx & (T_ - 1);
    const float* zin = fsl + (size_t)idx * D_;
    float z[D_], zs[D_];
#pragma unroll
    for (int d = 0; d < D_; d++) { z[d] = zin[d]; zs[d] = z[d]; }
#pragma unroll
    for (int i = 0; i < D_; i++) {
#pragma unroll
        for (int j = 0; j < D_ - 1; j++) {
            if (zs[j] < zs[j + 1]) { float tt = zs[j]; zs[j] = zs[j + 1]; zs[j + 1] = tt; }
        }
    }
    float csum[D_];
    float cs = 0.0f;
#pragma unroll
    for (int k = 0; k < D_; k++) { cs += zs[k]; csum[k] = cs; }
    int kz = 0;
#pragma unroll
    for (int k = 0; k < D_; k++) {
        if (1.0f + (float)(k + 1) * zs[k] > csum[k]) kz++;
    }
    float tau = (csum[kz - 1] - 1.0f) / (float)kz;
#pragma unroll
    for (int d = 0; d < D_; d++) {
        int jp = t * 3 + (d >> 1);
        g_sel_p[((size_t)jp * F_ + f) * 2 + (d & 1)] = fmaxf(z[d] - tau, 0.0f);
    }
}

// ---------------------------------------------------------------------------
// Kernel 2: 256-thread CTA, 16 batch rows, 2 CTAs/SM. Same per-thread issue
// mix as R10; co-resident CTAs overlap GEMM/eval phases.
// ---------------------------------------------------------------------------
__global__ __launch_bounds__(THREADS, 2) void odst_main(
    const float* __restrict__ x,
    const float* __restrict__ thr,
    const float* __restrict__ lt,
    const float* __restrict__ resp,
    float* __restrict__ out)
{
    extern __shared__ float smem[];
    float* x_t    = smem;                        // [256][XT_LD]   5120 f
    float* sel0   = x_t + 256 * XT_LD;           // [96][SEL_LD]   6528 f
    float* sel1   = sel0 + NPAIR * SEL_LD;       // [96][SEL_LD]   6528 f
    float* p_s    = sel1 + NPAIR * SEL_LD;       // [16][P_LD]     3152 f
    float* a_s    = p_s + 16 * P_LD;             // [192]
    float* b_s    = a_s + CCOLS;                 // [192]
    float* out_s  = b_s + CCOLS;                 // [16][16]        256 f

    const int tid  = threadIdx.x;
    const int row0 = blockIdx.x * BROWS;

    const uint32_t sel_u32[2] = { smem_u32(sel0), smem_u32(sel1) };

    out_s[tid] = 0.0f;

    // ---- load x tile TRANSPOSED: x_t[c][row], c=0..255, row=0..15 ----
    {
        const int c = tid;
        float tmp[16];
#pragma unroll
        for (int i = 0; i < 16; i++)
            tmp[i] = __ldg(&x[(size_t)(row0 + i) * F_ + c]);
#pragma unroll
        for (int i = 0; i < 4; i++) {
            float4 v = make_float4(tmp[4 * i], tmp[4 * i + 1],
                                   tmp[4 * i + 2], tmp[4 * i + 3]);
            *(float4*)&x_t[c * XT_LD + i * 4] = v;
        }
    }

    const int w    = tid >> 5;          // 0..7
    const int lane = tid & 31;

    // eval decomposition: half-warp per tree; 16 rows x 16 u per half-warp
    const int half = lane >> 4;         // 0/1: tree sub-slot
    const int hl   = lane & 15;
    const int rb   = (hl & 3) * 4;      // row base (4 rows of 16)
    const int ub   = (hl >> 2) * 4;     // u base (4 outputs)

    // GEMM decomposition: 2 rows x 6 cols (3 col-pairs) per thread
    const int rowg = tid & 7;           // 8 row groups of 2 rows
    const int colg = tid >> 3;          // 32 col groups of 6 cols
    const int r0g  = rowg * 2;
    const int c0   = colg * 6;
    const int jp0  = colg * 3;

    u64 accp[2][4];
#pragma unroll
    for (int pr = 0; pr < 2; pr++)
#pragma unroll
        for (int uu = 0; uu < 4; uu++) accp[pr][uu] = 0ull;

    for (int chunk = 0; chunk < NCHUNK; chunk++) {
        const int nbase = chunk * CCOLS;
        const int pbase = chunk * NPAIR;
        __syncthreads();  // prev chunk eval done; buffers free; x_t ready

        // ---- issue cp.async for kb=0 sel tile (96 jp x 32 k = 1536 chunks) ----
#pragma unroll
        for (int p = 0; p < 6; p++) {
            int c  = tid + p * 256;          // 0..1535
            int jp = c >> 4;                 // 16 chunks per jp row
            int co = (c & 15) * 4;           // float offset (0..60)
            const float* src = g_sel_p + (size_t)(pbase + jp) * (F_ * 2) + co;
            cpa16(sel_u32[0] + (uint32_t)(jp * SEL_LD + co) * 4u, src);
        }
        CP_COMMIT();

        if (tid < CCOLS) {
            float e = 0.5f * expf(-lt[nbase + tid]);
            a_s[tid] = e;
            b_s[tid] = 0.5f - e * thr[nbase + tid];
        }

        CP_WAIT0();
        __syncthreads();

        u64 fvA[3], fvB[3];
#pragma unroll
        for (int j = 0; j < 3; j++) { fvA[j] = 0ull; fvB[j] = 0ull; }

        for (int kb = 0; kb < NKB; kb++) {
            const float* cur = (kb & 1) ? sel1 : sel0;
            const uint32_t nxt_u32 = sel_u32[(kb + 1) & 1];

            if (kb < NKB - 1) {
#pragma unroll
                for (int p = 0; p < 6; p++) {
                    int c  = tid + p * 256;
                    int jp = c >> 4;
                    int co = (c & 15) * 4;
                    const float* src = g_sel_p + (size_t)(pbase + jp) * (F_ * 2)
                                     + (kb + 1) * (SELK * 2) + co;
                    cpa16(nxt_u32 + (uint32_t)(jp * SEL_LD + co) * 4u, src);
                }
                CP_COMMIT();
            }

            // compute: 8 iterations of 4 k-steps
            const float* selc = cur + jp0 * SEL_LD;
            const float* xb0  = x_t + (kb * SELK) * XT_LD + r0g;
#pragma unroll 4
            for (int kq = 0; kq < 8; kq++) {
                const int kbase = kq * 8;
                ulonglong2 q0a = *(const ulonglong2*)(selc + kbase);
                ulonglong2 q0b = *(const ulonglong2*)(selc + kbase + 4);
                ulonglong2 q1a = *(const ulonglong2*)(selc + SEL_LD + kbase);
                ulonglong2 q1b = *(const ulonglong2*)(selc + SEL_LD + kbase + 4);
                ulonglong2 q2a = *(const ulonglong2*)(selc + 2 * SEL_LD + kbase);
                ulonglong2 q2b = *(const ulonglong2*)(selc + 2 * SEL_LD + kbase + 4);
                const float* xk = xb0 + (kq * 4) * XT_LD;
                float2 x0 = *(const float2*)(xk);
                float2 x1 = *(const float2*)(xk + XT_LD);
                float2 x2 = *(const float2*)(xk + 2 * XT_LD);
                float2 x3 = *(const float2*)(xk + 3 * XT_LD);

                u64 xa, xb;
                xa = pkdup(x0.x); xb = pkdup(x0.y);
                fvA[0] = fma2(xa, q0a.x, fvA[0]);
                fvA[1] = fma2(xa, q1a.x, fvA[1]);
                fvA[2] = fma2(xa, q2a.x, fvA[2]);
                fvB[0] = fma2(xb, q0a.x, fvB[0]);
                fvB[1] = fma2(xb, q1a.x, fvB[1]);
                fvB[2] = fma2(xb, q2a.x, fvB[2]);
                xa = pkdup(x1.x); xb = pkdup(x1.y);
                fvA[0] = fma2(xa, q0a.y, fvA[0]);
                fvA[1] = fma2(xa, q1a.y, fvA[1]);
                fvA[2] = fma2(xa, q2a.y, fvA[2]);
                fvB[0] = fma2(xb, q0a.y, fvB[0]);
                fvB[1] = fma2(xb, q1a.y, fvB[1]);
                fvB[2] = fma2(xb, q2a.y, fvB[2]);
                xa = pkdup(x2.x); xb = pkdup(x2.y);
                fvA[0] = fma2(xa, q0b.x, fvA[0]);
                fvA[1] = fma2(xa, q1b.x, fvA[1]);
                fvA[2] = fma2(xa, q2b.x, fvA[2]);
                fvB[0] = fma2(xb, q0b.x, fvB[0]);
                fvB[1] = fma2(xb, q1b.x, fvB[1]);
                fvB[2] = fma2(xb, q2b.x, fvB[2]);
                xa = pkdup(x3.x); xb = pkdup(x3.y);
                fvA[0] = fma2(xa, q0b.y, fvA[0]);
                fvA[1] = fma2(xa, q1b.y, fvA[1]);
                fvA[2] = fma2(xa, q2b.y, fvA[2]);
                fvB[0] = fma2(xb, q0b.y, fvB[0]);
                fvB[1] = fma2(xb, q1b.y, fvB[1]);
                fvB[2] = fma2(xb, q2b.y, fvB[2]);
            }

            if (kb < NKB - 1) {
                CP_WAIT0();
                __syncthreads();
            }
        }

        // sparsemoid: rows r0g..r0g+1, cols c0..c0+5
#pragma unroll
        for (int j = 0; j < 3; j++) {
            int cc = c0 + 2 * j;
            float fa0 = lo32(fvA[j]), fa1 = hi32(fvA[j]);
            float fb0 = lo32(fvB[j]), fb1 = hi32(fvB[j]);
            p_s[r0g * P_LD + cc]           = __saturatef(fmaf(a_s[cc],     fa0, b_s[cc]));
            p_s[r0g * P_LD + cc + 1]       = __saturatef(fmaf(a_s[cc + 1], fa1, b_s[cc + 1]));
            p_s[(r0g + 1) * P_LD + cc]     = __saturatef(fmaf(a_s[cc],     fb0, b_s[cc]));
            p_s[(r0g + 1) * P_LD + cc + 1] = __saturatef(fmaf(a_s[cc + 1], fb1, b_s[cc + 1]));
        }
        __syncthreads();

        // ---- eval: half-warp (w,half) handles trees chunk*32 + {2w+half, 16+2w+half} ----
        for (int it = 0; it < 2; it++) {
            const int tloc = it * 16 + w * 2 + half;
            const int tg   = chunk * 32 + tloc;
            const float4* rg = (const float4*)(resp + (size_t)tg * (U_ * NB_));

            const int pc = tloc * 6;
            u64 r01p[2][4], r23p[2][4], r45p[2][4];
#pragma unroll
            for (int pr = 0; pr < 2; pr++) {
                const float* prow0 = p_s + (rb + 2 * pr) * P_LD + pc;
                const float* prow1 = prow0 + P_LD;
                u64 P0 = pk(prow0[0], prow1[0]);
                u64 P1 = pk(prow0[1], prow1[1]);
                u64 P2 = pk(prow0[2], prow1[2]);
                u64 P3 = pk(prow0[3], prow1[3]);
                u64 P4 = pk(prow0[4], prow1[4]);
                u64 P5 = pk(prow0[5], prow1[5]);
                const u64 ONE = 0x3f8000003f800000ull;
                const u64 NEG = 0xbf800000bf800000ull;
                u64 Q0 = fma2(P0, NEG, ONE);
                u64 Q1 = fma2(P1, NEG, ONE);
                u64 Q2 = fma2(P2, NEG, ONE);
                u64 Q3 = fma2(P3, NEG, ONE);
                u64 Q4 = fma2(P4, NEG, ONE);
                u64 Q5 = fma2(P5, NEG, ONE);
                r01p[pr][0] = mul2(P0, P1); r01p[pr][1] = mul2(Q0, P1);
                r01p[pr][2] = mul2(P0, Q1); r01p[pr][3] = mul2(Q0, Q1);
                r23p[pr][0] = mul2(P2, P3); r23p[pr][1] = mul2(Q2, P3);
                r23p[pr][2] = mul2(P2, Q3); r23p[pr][3] = mul2(Q2, Q3);
                r45p[pr][0] = mul2(P4, P5); r45p[pr][1] = mul2(Q4, P5);
                r45p[pr][2] = mul2(P4, Q5); r45p[pr][3] = mul2(Q4, Q5);
            }

#pragma unroll
            for (int j45 = 0; j45 < 4; j45++) {
#pragma unroll
                for (int j23 = 0; j23 < 4; j23++) {
                    u64 t2p0 = mul2(r45p[0][j45], r23p[0][j23]);
                    u64 t2p1 = mul2(r45p[1][j45], r23p[1][j23]);
                    const int cq = j45 * 4 + j23;
                    float4 rv0 = __ldg(&rg[(ub + 0) * 16 + cq]);
                    float4 rv1 = __ldg(&rg[(ub + 1) * 16 + cq]);
                    float4 rv2 = __ldg(&rg[(ub + 2) * 16 + cq]);
                    float4 rv3 = __ldg(&rg[(ub + 3) * 16 + cq]);
#pragma unroll
                    for (int j01 = 0; j01 < 4; j01++) {
                        u64 rw0 = mul2(t2p0, r01p[0][j01]);
                        u64 rw1 = mul2(t2p1, r01p[1][j01]);
                        u64 e0 = pkdup(f4get(rv0, j01));
                        u64 e1 = pkdup(f4get(rv1, j01));
                        u64 e2 = pkdup(f4get(rv2, j01));
                        u64 e3 = pkdup(f4get(rv3, j01));
                        accp[0][0] = fma2(rw0, e0, accp[0][0]);
                        accp[0][1] = fma2(rw0, e1, accp[0][1]);
                        accp[0][2] = fma2(rw0, e2, accp[0][2]);
                        accp[0][3] = fma2(rw0, e3, accp[0][3]);
                        accp[1][0] = fma2(rw1, e0, accp[1][0]);
                        accp[1][1] = fma2(rw1, e1, accp[1][1]);
                        accp[1][2] = fma2(rw1, e2, accp[1][2]);
                        accp[1][3] = fma2(rw1, e3, accp[1][3]);
                    }
                }
            }
        }
    }

    // unpack accumulators
    float acc[4][4];
#pragma unroll
    for (int pr = 0; pr < 2; pr++)
#pragma unroll
        for (int uu = 0; uu < 4; uu++) {
            acc[2 * pr + 0][uu] = lo32(accp[pr][uu]);
            acc[2 * pr + 1][uu] = hi32(accp[pr][uu]);
        }

    // deterministic reduction over the 16 (warp, half) tree slots
    for (int pass = 0; pass < 16; pass++) {
        __syncthreads();
        if (w * 2 + half == pass) {
#pragma unroll
            for (int rr = 0; rr < 4; rr++)
#pragma unroll
                for (int uu = 0; uu < 4; uu++)
                    out_s[(rb + rr) * U_ + ub + uu] += acc[rr][uu];
        }
    }
    __syncthreads();

    // write output: 16 rows x 16 u = 256 floats, one per thread
    out[(size_t)row0 * U_ + tid] = out_s[tid];
}

// ---------------------------------------------------------------------------
extern "C" void kernel_launch(void* const* d_in, const int* in_sizes, int n_in,
                              void* d_out, int out_size) {
    const float* x    = (const float*)d_in[0];
    const float* fsl  = (const float*)d_in[1];
    const float* thr  = (const float*)d_in[2];
    const float* lt   = (const float*)d_in[3];
    const float* resp = (const float*)d_in[4];
    float* out = (float*)d_out;

    const int smem_bytes =
        (256 * XT_LD + 2 * NPAIR * SEL_LD + 16 * P_LD + 2 * CCOLS + 256)
        * (int)sizeof(float);   // 87,872 B -> 2 CTAs/SM

    cudaFuncSetAttribute(odst_main, cudaFuncAttributeMaxDynamicSharedMemorySize,
                         smem_bytes);

    sparsemax_kernel<<<(F_ * T_) / 256, 256>>>(fsl);
    odst_main<<<(4096 / BROWS), THREADS, smem_bytes>>>(x, thr, lt, resp, out);
}